// round 1
// baseline (speedup 1.0000x reference)
#include <cuda_runtime.h>
#include <math.h>

// LIANetLight hash-grid encoder.
// Inputs (metadata order):
//  0: x0      float32 [B]
//  1: y0      float32 [B]
//  2: tables  float32 [T, 2]
//  3: seeds   uint32  [L]
//  4: level_N float32 [L]
//  5: memorized_crop_size (scalar)
//  6: complete_tile_size  (scalar)
// Output: float32 [B, L*2, H, W]

#define HASH_P1 2654435761u
#define HASH_P2 805459861u

// Read a scalar that may have been stored as int32 or float32.
__device__ __forceinline__ float read_scalar_as_float(const int* p) {
    int v = *p;
    // plausible small positive int => it was stored as int32
    if (v > 0 && v < (1 << 24)) return (float)v;
    // otherwise reinterpret the bits as float
    return __int_as_float(v);
}

template <int LFIX, bool POW2>
__global__ void __launch_bounds__(256)
hashenc_kernel(const float* __restrict__ x0,
               const float* __restrict__ y0,
               const float2* __restrict__ tables,
               const unsigned int* __restrict__ seeds,
               const float* __restrict__ levelN,
               const int* __restrict__ tile_ptr,
               float* __restrict__ out,
               int B, int H, int Lrt,
               unsigned int T, unsigned int mask)
{
    const int L = (LFIX > 0) ? LFIX : Lrt;

    __shared__ float s_scale[64];
    __shared__ unsigned int s_seed[64];
    if (threadIdx.x < L) {
        float tf = read_scalar_as_float(tile_ptr);
        s_scale[threadIdx.x] = levelN[threadIdx.x] / tf;
        s_seed[threadIdx.x]  = seeds[threadIdx.x];
    }
    __syncthreads();

    const int HW = H * H;
    const long long total = (long long)B * HW;
    const long long tid = (long long)blockIdx.x * blockDim.x + threadIdx.x;
    if (tid >= total) return;

    const int pix = (int)(tid % HW);
    const int b   = (int)(tid / HW);
    const int w   = pix % H;
    const int h   = pix / H;

    const float px = (float)w + x0[b];
    const float py = (float)h + y0[b];

    float* outb = out + (size_t)b * (size_t)(2 * L) * (size_t)HW + pix;

    #pragma unroll
    for (int l = 0; l < L; l++) {
        const float sc = s_scale[l];
        const float xn = px * sc;
        const float yn = py * sc;
        const float fx0f = floorf(xn);
        const float fy0f = floorf(yn);
        const int ix0 = (int)fx0f;
        const int iy0 = (int)fy0f;
        const float fx = xn - fx0f;
        const float fy = yn - fy0f;

        const unsigned int se  = s_seed[l];
        const unsigned int hx0 = (unsigned int)ix0 * HASH_P1;
        const unsigned int hx1 = hx0 + HASH_P1;   // (ix0+1)*P1 mod 2^32
        const unsigned int hy0 = (unsigned int)iy0 * HASH_P2;
        const unsigned int hy1 = hy0 + HASH_P2;   // (iy0+1)*P2 mod 2^32

        unsigned int i00, i10, i01, i11;
        if (POW2) {
            i00 = (hx0 ^ hy0 ^ se) & mask;
            i10 = (hx1 ^ hy0 ^ se) & mask;
            i01 = (hx0 ^ hy1 ^ se) & mask;
            i11 = (hx1 ^ hy1 ^ se) & mask;
        } else {
            i00 = (hx0 ^ hy0 ^ se) % T;
            i10 = (hx1 ^ hy0 ^ se) % T;
            i01 = (hx0 ^ hy1 ^ se) % T;
            i11 = (hx1 ^ hy1 ^ se) % T;
        }

        const float2 f00 = __ldg(&tables[i00]);
        const float2 f10 = __ldg(&tables[i10]);
        const float2 f01 = __ldg(&tables[i01]);
        const float2 f11 = __ldg(&tables[i11]);

        const float gx = 1.0f - fx;
        const float gy = 1.0f - fy;
        const float w00 = gx * gy;
        const float w10 = fx * gy;
        const float w01 = gx * fy;
        const float w11 = fx * fy;

        const float ex = w00 * f00.x + w10 * f10.x + w01 * f01.x + w11 * f11.x;
        const float ey = w00 * f00.y + w10 * f10.y + w01 * f01.y + w11 * f11.y;

        outb[(size_t)(2 * l)     * (size_t)HW] = ex;
        outb[(size_t)(2 * l + 1) * (size_t)HW] = ey;
    }
}

extern "C" void kernel_launch(void* const* d_in, const int* in_sizes, int n_in,
                              void* d_out, int out_size)
{
    const float*        x0     = (const float*)d_in[0];
    const float*        y0     = (const float*)d_in[1];
    const float2*       tables = (const float2*)d_in[2];
    const unsigned int* seeds  = (const unsigned int*)d_in[3];
    const float*        levelN = (const float*)d_in[4];
    const int*          tile   = (const int*)d_in[6];   // complete_tile_size scalar
    float*              out    = (float*)d_out;

    const int B = in_sizes[0];
    const int L = in_sizes[3];
    const unsigned int T = (unsigned int)(in_sizes[2] / 2);   // FEAT_DIM = 2

    // H from output size: out_size = B * 2L * H * H
    const long long hw = (long long)out_size / ((long long)B * 2LL * (long long)L);
    int H = (int)(sqrt((double)hw) + 0.5);

    const bool pow2 = (T & (T - 1)) == 0;
    const unsigned int mask = T - 1;

    const long long total = (long long)B * H * H;
    const int threads = 256;
    const int blocks = (int)((total + threads - 1) / threads);

    if (L == 16) {
        if (pow2)
            hashenc_kernel<16, true><<<blocks, threads>>>(x0, y0, tables, seeds, levelN,
                                                          tile, out, B, H, L, T, mask);
        else
            hashenc_kernel<16, false><<<blocks, threads>>>(x0, y0, tables, seeds, levelN,
                                                           tile, out, B, H, L, T, mask);
    } else {
        if (pow2)
            hashenc_kernel<0, true><<<blocks, threads>>>(x0, y0, tables, seeds, levelN,
                                                         tile, out, B, H, L, T, mask);
        else
            hashenc_kernel<0, false><<<blocks, threads>>>(x0, y0, tables, seeds, levelN,
                                                          tile, out, B, H, L, T, mask);
    }
}